// round 4
// baseline (speedup 1.0000x reference)
#include <cuda_runtime.h>
#include <cuda_bf16.h>
#include <math.h>

// Problem constants
#define BF      96          // B * MAX_FRAMES
#define NTOK    197
#define NSP     196
#define DIM     512
#define HID     256
#define TOPK    49
#define NS      256
#define SIGMA   0.05f
#define M1      (BF*NTOK)   // 18912 rows for GEMM1
#define M3      (BF*NSP)    // 18816 rows for score (== 294*64 exactly)

typedef unsigned long long u64;

// ---------------- scratch ----------------
__device__ float g_h[BF*NTOK*HID];       // gelu(LN(x)@w_in)
__device__ float g_stats[2*M1];          // per-row mu, rstd
__device__ float g_gc[BF*HID];           // h[f,0,:] @ w1[256:,:]
__device__ float g_score[BF*NSP];        // spatial scores

__device__ __forceinline__ float gelu_exact(float v){
    return 0.5f * v * (1.0f + erff(v * 0.70710678118654752440f));
}

// ---- packed fp32x2 (Blackwell) : bitwise identical to 2x scalar fmaf ----
__device__ __forceinline__ void ffma2(u64 &d, u64 a, u64 b){
    asm("fma.rn.f32x2 %0, %1, %2, %0;" : "+l"(d) : "l"(a), "l"(b));
}
__device__ __forceinline__ u64 pk2(float lo, float hi){
    u64 r; asm("mov.b64 %0, {%1, %2};" : "=l"(r) : "f"(lo), "f"(hi)); return r;
}
__device__ __forceinline__ void upk2(u64 v, float &lo, float &hi){
    asm("mov.b64 {%0, %1}, %2;" : "=f"(lo), "=f"(hi) : "l"(v));
}

// ---------------- K0: per-row mean / rstd (1 warp per row) ----------------
__global__ void stats_kernel(const float* __restrict__ x){
    int wid = threadIdx.x >> 5, lane = threadIdx.x & 31;
    int row = blockIdx.x*8 + wid;
    if (row >= M1) return;
    const float* xr = x + (size_t)row*DIM;
    float4 v[4];
    float s = 0.f;
    #pragma unroll
    for (int i=0;i<4;i++){
        v[i] = *(const float4*)(xr + i*128 + lane*4);
        s += v[i].x + v[i].y + v[i].z + v[i].w;
    }
    #pragma unroll
    for (int o=16;o>0;o>>=1) s += __shfl_xor_sync(0xFFFFFFFFu, s, o);
    float mu = s * (1.0f/DIM);
    float sq = 0.f;
    #pragma unroll
    for (int i=0;i<4;i++){
        float a=v[i].x-mu, b=v[i].y-mu, c=v[i].z-mu, d=v[i].w-mu;
        sq += a*a + b*b + c*c + d*d;
    }
    #pragma unroll
    for (int o=16;o>0;o>>=1) sq += __shfl_xor_sync(0xFFFFFFFFu, sq, o);
    if (lane==0){
        g_stats[2*row]   = mu;
        g_stats[2*row+1] = rsqrtf(sq * (1.0f/DIM) + 1e-5f);
    }
}

// ---------------- K1: h = gelu(LN(x) @ w_in)  (M1 x 512 x 256) ----------------
// BM=64, BN=256 (full), BK=8, 256 threads (8 warps), 2 CTAs/SM.
// Warp = 8 rows x 256 cols; thread = 4 row-pairs x 8 cols. B scalar LDS + reg dup.
__global__ __launch_bounds__(256,2) void gemm1_kernel(const float* __restrict__ x,
                             const float* __restrict__ gamma,
                             const float* __restrict__ beta,
                             const float* __restrict__ w){
    __shared__ float As[2][8][64];    // 2 KB/buf
    __shared__ float Bs[2][8][256];   // 8 KB/buf
    int tid = threadIdx.x;
    int lane = tid & 31, wid = tid >> 5;
    int m0 = blockIdx.x * 64;

    // A loader: row = tid&63, two k's at (tid>>6)*2
    int arow = tid & 63;
    int ak   = (tid >> 6) * 2;           // 0,2,4,6
    int gm = m0 + arow;
    bool av = gm < M1;
    float mu = 0.f, rs = 0.f;
    if (av){ mu = g_stats[2*gm]; rs = g_stats[2*gm+1]; }
    const float* xrow = x + (size_t)gm*DIM;
    // B loader: k = tid>>5 (0..7), n = (tid&31)*8  (two float4)
    int bk = tid >> 5;
    int bn = (tid & 31) * 8;

    u64 acc[4][8];
    #pragma unroll
    for (int i=0;i<4;i++)
        #pragma unroll
        for (int j=0;j<8;j++) acc[i][j] = 0ull;

    float2 va; float4 wb0, wb1;
    {
        if (av){
            float2 xa = *(const float2*)(xrow + ak);
            float2 ga = *(const float2*)(gamma + ak);
            float2 ba = *(const float2*)(beta  + ak);
            va.x = (xa.x-mu)*rs*ga.x + ba.x;
            va.y = (xa.y-mu)*rs*ga.y + ba.y;
        } else va = make_float2(0.f,0.f);
        wb0 = *(const float4*)(w + (size_t)bk*HID + bn);
        wb1 = *(const float4*)(w + (size_t)bk*HID + bn + 4);
    }
    As[0][ak][arow]   = va.x;
    As[0][ak+1][arow] = va.y;
    *(float4*)&Bs[0][bk][bn]   = wb0;
    *(float4*)&Bs[0][bk][bn+4] = wb1;
    __syncthreads();

    int buf = 0;
    const int T = DIM/8;   // 64
    for (int t=0; t<T; t++){
        if (t+1 < T){
            int k0 = (t+1)*8;
            if (av){
                float2 xa = *(const float2*)(xrow + k0 + ak);
                float2 ga = *(const float2*)(gamma + k0 + ak);
                float2 ba = *(const float2*)(beta  + k0 + ak);
                va.x = (xa.x-mu)*rs*ga.x + ba.x;
                va.y = (xa.y-mu)*rs*ga.y + ba.y;
            } else va = make_float2(0.f,0.f);
            wb0 = *(const float4*)(w + (size_t)(k0+bk)*HID + bn);
            wb1 = *(const float4*)(w + (size_t)(k0+bk)*HID + bn + 4);
        }
        #pragma unroll
        for (int kk=0;kk<8;kk++){
            const u64* ap = (const u64*)&As[buf][kk][wid*8];
            u64 a0 = ap[0], a1 = ap[1], a2 = ap[2], a3 = ap[3];
            #pragma unroll
            for (int jj=0;jj<8;jj++){
                float bv = Bs[buf][kk][lane + 32*jj];
                u64 b2 = pk2(bv, bv);
                ffma2(acc[0][jj], a0, b2);
                ffma2(acc[1][jj], a1, b2);
                ffma2(acc[2][jj], a2, b2);
                ffma2(acc[3][jj], a3, b2);
            }
        }
        if (t+1 < T){
            int nb = buf ^ 1;
            As[nb][ak][arow]   = va.x;
            As[nb][ak+1][arow] = va.y;
            *(float4*)&Bs[nb][bk][bn]   = wb0;
            *(float4*)&Bs[nb][bk][bn+4] = wb1;
            __syncthreads();
            buf = nb;
        }
    }
    // epilogue: gelu + store
    int r0 = m0 + wid*8;
    #pragma unroll
    for (int rp=0;rp<4;rp++){
        int rlo = r0 + 2*rp, rhi = rlo + 1;
        bool slo = rlo < M1, shi = rhi < M1;
        #pragma unroll
        for (int jj=0;jj<8;jj++){
            float lo, hi;
            upk2(acc[rp][jj], lo, hi);
            int col = lane + 32*jj;
            if (slo) g_h[(size_t)rlo*HID + col] = gelu_exact(lo);
            if (shi) g_h[(size_t)rhi*HID + col] = gelu_exact(hi);
        }
    }
}

// ---------------- K2: gcontrib[f,j] = sum_k h[f,0,k] * w1[256+k, j] ----------------
__global__ void gc_kernel(const float* __restrict__ w1){
    __shared__ float h0[HID];
    int f = blockIdx.x, j = threadIdx.x;
    h0[j] = g_h[(size_t)(f*NTOK)*HID + j];
    __syncthreads();
    float acc = 0.f;
    #pragma unroll 8
    for (int k=0;k<HID;k++)
        acc += h0[k] * w1[(size_t)(HID+k)*HID + j];
    g_gc[f*HID + j] = acc;
}

// ---------------- K3: score = tanh(gelu(h@w1_top + gc) @ w2) ----------------
// BM=64, BN=256 (reduced in epilogue), BK=8, 256 threads, 2 CTAs/SM.
__global__ __launch_bounds__(256,2) void score_kernel(const float* __restrict__ w1,
                             const float* __restrict__ w2){
    __shared__ float As[2][8][64];
    __shared__ float Bs[2][8][256];
    int tid = threadIdx.x;
    int lane = tid & 31, wid = tid >> 5;
    int m0 = blockIdx.x * 64;

    // A loader
    int arow = tid & 63;
    int ak   = (tid >> 6) * 2;
    int m = m0 + arow;
    int f_ld = m / NSP;
    int i_ld = m - f_ld*NSP;
    const float* hrow = g_h + (size_t)(f_ld*NTOK + 1 + i_ld)*HID;
    // B loader
    int bk = tid >> 5;
    int bn = (tid & 31) * 8;

    u64 acc[4][8];
    #pragma unroll
    for (int i=0;i<4;i++)
        #pragma unroll
        for (int j=0;j<8;j++) acc[i][j] = 0ull;

    float2 va; float4 wb0, wb1;
    {
        va = *(const float2*)(hrow + ak);
        wb0 = *(const float4*)(w1 + (size_t)bk*HID + bn);
        wb1 = *(const float4*)(w1 + (size_t)bk*HID + bn + 4);
    }
    As[0][ak][arow]   = va.x;
    As[0][ak+1][arow] = va.y;
    *(float4*)&Bs[0][bk][bn]   = wb0;
    *(float4*)&Bs[0][bk][bn+4] = wb1;
    __syncthreads();

    int buf = 0;
    const int T = HID/8;  // 32
    for (int t=0;t<T;t++){
        if (t+1 < T){
            int k0 = (t+1)*8;
            va = *(const float2*)(hrow + k0 + ak);
            wb0 = *(const float4*)(w1 + (size_t)(k0+bk)*HID + bn);
            wb1 = *(const float4*)(w1 + (size_t)(k0+bk)*HID + bn + 4);
        }
        #pragma unroll
        for (int kk=0;kk<8;kk++){
            const u64* ap = (const u64*)&As[buf][kk][wid*8];
            u64 a0 = ap[0], a1 = ap[1], a2 = ap[2], a3 = ap[3];
            #pragma unroll
            for (int jj=0;jj<8;jj++){
                float bv = Bs[buf][kk][lane + 32*jj];
                u64 b2 = pk2(bv, bv);
                ffma2(acc[0][jj], a0, b2);
                ffma2(acc[1][jj], a1, b2);
                ffma2(acc[2][jj], a2, b2);
                ffma2(acc[3][jj], a3, b2);
            }
        }
        if (t+1 < T){
            int nb = buf ^ 1;
            As[nb][ak][arow]   = va.x;
            As[nb][ak+1][arow] = va.y;
            *(float4*)&Bs[nb][bk][bn]   = wb0;
            *(float4*)&Bs[nb][bk][bn+4] = wb1;
            __syncthreads();
            buf = nb;
        }
    }
    // epilogue: u + gc -> gelu -> *w2 -> row reduce (rows wid*8..+8, cols lane+32jj)
    int rbase = m0 + wid*8;
    int fr[8];
    #pragma unroll
    for (int rr=0;rr<8;rr++) fr[rr] = (rbase + rr) / NSP;
    float s[8];
    #pragma unroll
    for (int rr=0;rr<8;rr++) s[rr] = 0.f;
    #pragma unroll
    for (int jj=0;jj<8;jj++){
        int j = lane + 32*jj;
        float w2v = w2[j];
        #pragma unroll
        for (int rp=0;rp<4;rp++){
            float lo, hi;
            upk2(acc[rp][jj], lo, hi);
            float glo = g_gc[fr[2*rp]*HID + j];
            float ghi = g_gc[fr[2*rp+1]*HID + j];
            s[2*rp]   += gelu_exact(lo + glo) * w2v;
            s[2*rp+1] += gelu_exact(hi + ghi) * w2v;
        }
    }
    #pragma unroll
    for (int rr=0;rr<8;rr++){
        float v = s[rr];
        #pragma unroll
        for (int o=16;o>0;o>>=1) v += __shfl_xor_sync(0xFFFFFFFFu, v, o);
        s[rr] = v;
    }
    if (lane == 0){
        #pragma unroll
        for (int rr=0;rr<8;rr++)
            g_score[rbase + rr] = tanhf(s[rr]);
    }
}

// ---------------- K4: fused select (top-49, exact) + output GEMM ----------------
// grid = BF (96) blocks, 512 threads. ind lives only in smem.
// Phase 1: 16 warps x 16 samples; exact 49th key via 40-bit binary search;
//          atomicAdd of exact dyadic 1/256 into smem ind (order-independent).
// Phase 2: out[bf] = [cls ; ind^T applied to spat], thread = one d of 512.
__global__ __launch_bounds__(512) void select_output_kernel(
        const float* __restrict__ noise,
        const float* __restrict__ x,
        float* __restrict__ out){
    __shared__ float sps[NSP];
    __shared__ __align__(8) float indsT[NSP][TOPK+1];  // [l][k] padded to 50 -> 39.2 KB
    int bf = blockIdx.x;
    int tid = threadIdx.x;
    int lane = tid & 31, wid = tid >> 5;

    if (tid < NSP) sps[tid] = g_score[bf*NSP + tid];
    for (int i=tid; i<NSP*(TOPK+1); i+=512) ((float*)indsT)[i] = 0.f;
    __syncthreads();

    // ---- Phase 1: selection (warp wid handles samples wid*16 .. +16) ----
    for (int s8=0; s8<16; s8++){
        int s = wid*16 + s8;
        const float* np = noise + (size_t)(bf*NS + s)*NSP;
        u64 K[7];
        #pragma unroll
        for (int c=0;c<7;c++){
            int l = c*32 + lane;
            u64 kk = 0ull;
            if (l < NSP){
                float p = sps[l] + SIGMA * np[l];
                unsigned u = __float_as_uint(p);
                u ^= (u & 0x80000000u) ? 0xFFFFFFFFu : 0x80000000u;   // monotone key
                kk = ((u64)u << 8) | (unsigned)(255 - l);             // tie: lower l wins
            }
            K[c] = kk;
        }
        u64 pref = 0ull;
        #pragma unroll 1
        for (int b=39;b>=0;b--){
            u64 cand = pref | (1ull << b);
            unsigned cnt = 0;
            #pragma unroll
            for (int c=0;c<7;c++) cnt += (K[c] >= cand) ? 1u : 0u;
            cnt = __reduce_add_sync(0xFFFFFFFFu, cnt);
            if (cnt >= TOPK) pref = cand;
        }
        int pre = 0;
        #pragma unroll
        for (int c=0;c<7;c++){
            bool sel = (K[c] >= pref);
            unsigned bal = __ballot_sync(0xFFFFFFFFu, sel);
            int l = c*32 + lane;
            if (sel){
                int k = pre + __popc(bal & ((1u<<lane)-1u));
                atomicAdd(&indsT[l][k], 1.0f/NS);
            }
            pre += __popc(bal);
        }
    }
    __syncthreads();

    // ---- Phase 2: out = [cls ; ind @ spat] ----
    int d = tid;
    u64 acc[25];
    #pragma unroll
    for (int kp=0;kp<25;kp++) acc[kp] = 0ull;
    const float* xb = x + (size_t)(bf*NTOK)*DIM + d;
    #pragma unroll 1
    for (int l=0;l<NSP;l++){
        float xv = xb[(size_t)(l+1)*DIM];
        u64 x2 = pk2(xv, xv);
        const u64* row = (const u64*)indsT[l];
        #pragma unroll
        for (int kp=0;kp<25;kp++) ffma2(acc[kp], x2, row[kp]);
    }
    float* ob = out + (size_t)(bf*(1+TOPK))*DIM + d;
    ob[0] = xb[0];   // cls passthrough
    #pragma unroll
    for (int kp=0;kp<25;kp++){
        float lo, hi;
        upk2(acc[kp], lo, hi);
        ob[(size_t)(2*kp+1)*DIM] = lo;
        if (kp < 24) ob[(size_t)(2*kp+2)*DIM] = hi;
    }
}

// ---------------- launcher ----------------
extern "C" void kernel_launch(void* const* d_in, const int* in_sizes, int n_in,
                              void* d_out, int out_size){
    const float* x     = (const float*)d_in[0];
    const float* noise = (const float*)d_in[1];
    const float* gamma = (const float*)d_in[2];
    const float* beta  = (const float*)d_in[3];
    const float* w_in  = (const float*)d_in[4];
    const float* w1    = (const float*)d_in[5];
    const float* w2    = (const float*)d_in[6];
    float* out = (float*)d_out;

    stats_kernel<<<(M1+7)/8, 256>>>(x);
    gemm1_kernel<<<(M1+63)/64, 256>>>(x, gamma, beta, w_in);
    gc_kernel<<<BF, 256>>>(w1);
    score_kernel<<<M3/64, 256>>>(w1, w2);
    select_output_kernel<<<BF, 512>>>(noise, x, out);
}

// round 5
// speedup vs baseline: 1.0224x; 1.0224x over previous
#include <cuda_runtime.h>
#include <cuda_bf16.h>
#include <math.h>

// Problem constants
#define BF      96          // B * MAX_FRAMES
#define NTOK    197
#define NSP     196
#define DIM     512
#define HID     256
#define TOPK    49
#define NS      256
#define SIGMA   0.05f
#define M1      (BF*NTOK)   // 18912 rows for GEMM1
#define M3      (BF*NSP)    // 18816 rows for score (== 147*128 exactly)

typedef unsigned long long u64;

// ---------------- scratch ----------------
__device__ float g_h[BF*NTOK*HID];       // gelu(LN(x)@w_in)
__device__ float g_stats[2*M1];          // per-row mu, rstd
__device__ float g_gc[BF*HID];           // h[f,0,:] @ w1[256:,:]
__device__ float g_score[BF*NSP];        // spatial scores
__device__ float g_ind[BF*TOPK*NSP];     // selection weights (zeroed in stats_kernel)

__device__ __forceinline__ float gelu_exact(float v){
    return 0.5f * v * (1.0f + erff(v * 0.70710678118654752440f));
}

// ---- packed fp32x2 (Blackwell) : bitwise identical to 2x scalar fmaf ----
__device__ __forceinline__ void ffma2(u64 &d, u64 a, u64 b){
    asm("fma.rn.f32x2 %0, %1, %2, %0;" : "+l"(d) : "l"(a), "l"(b));
}
__device__ __forceinline__ u64 pk2(float lo, float hi){
    u64 r; asm("mov.b64 %0, {%1, %2};" : "=l"(r) : "f"(lo), "f"(hi)); return r;
}
__device__ __forceinline__ void upk2(u64 v, float &lo, float &hi){
    asm("mov.b64 {%0, %1}, %2;" : "=f"(lo), "=f"(hi) : "l"(v));
}

// ---------------- K0: per-row mean / rstd (1 warp per row) + zero g_ind ----------------
__global__ void stats_kernel(const float* __restrict__ x){
    // grid-stride zero of g_ind (independent of stats; consumed 3 kernels later)
    {
        int gt = blockIdx.x*256 + threadIdx.x;
        int nthr = gridDim.x*256;
        for (int i=gt; i<BF*TOPK*NSP; i+=nthr) g_ind[i] = 0.f;
    }
    int wid = threadIdx.x >> 5, lane = threadIdx.x & 31;
    int row = blockIdx.x*8 + wid;
    if (row >= M1) return;
    const float* xr = x + (size_t)row*DIM;
    float4 v[4];
    float s = 0.f;
    #pragma unroll
    for (int i=0;i<4;i++){
        v[i] = *(const float4*)(xr + i*128 + lane*4);
        s += v[i].x + v[i].y + v[i].z + v[i].w;
    }
    #pragma unroll
    for (int o=16;o>0;o>>=1) s += __shfl_xor_sync(0xFFFFFFFFu, s, o);
    float mu = s * (1.0f/DIM);
    float sq = 0.f;
    #pragma unroll
    for (int i=0;i<4;i++){
        float a=v[i].x-mu, b=v[i].y-mu, c=v[i].z-mu, d=v[i].w-mu;
        sq += a*a + b*b + c*c + d*d;
    }
    #pragma unroll
    for (int o=16;o>0;o>>=1) sq += __shfl_xor_sync(0xFFFFFFFFu, sq, o);
    if (lane==0){
        g_stats[2*row]   = mu;
        g_stats[2*row+1] = rsqrtf(sq * (1.0f/DIM) + 1e-5f);
    }
}

// ---------------- K1: h = gelu(LN(x) @ w_in)  (M1 x 512 x 256) ----------------
// BM=128, BN=256 (full), BK=16, 512 threads (16 warps), grid 148 (1 wave).
// Warp = 8 rows x 256 cols; thread = 4 row-pairs x 8 cols. B scalar LDS + reg dup.
__global__ __launch_bounds__(512,1) void gemm1_kernel(const float* __restrict__ x,
                             const float* __restrict__ gamma,
                             const float* __restrict__ beta,
                             const float* __restrict__ w){
    __shared__ float As[2][16][128];   // 8 KB/buf
    __shared__ float Bs[2][16][256];   // 16 KB/buf
    int tid = threadIdx.x;
    int lane = tid & 31, wid = tid >> 5;
    int m0 = blockIdx.x * 128;

    // A loader: row = tid&127, four k's at (tid>>7)*4
    int arow = tid & 127;
    int ak   = (tid >> 7) * 4;           // 0,4,8,12
    int gm = m0 + arow;
    bool av = gm < M1;
    float mu = 0.f, rs = 0.f;
    if (av){ mu = g_stats[2*gm]; rs = g_stats[2*gm+1]; }
    const float* xrow = x + (size_t)gm*DIM;
    // B loader: k = tid>>5 (0..15), n = (tid&31)*8  (two float4)
    int bk = tid >> 5;
    int bn = (tid & 31) * 8;

    u64 acc[4][8];
    #pragma unroll
    for (int i=0;i<4;i++)
        #pragma unroll
        for (int j=0;j<8;j++) acc[i][j] = 0ull;

    float4 va; float4 wb0, wb1;
    {
        if (av){
            float4 xa = *(const float4*)(xrow + ak);
            float4 ga = *(const float4*)(gamma + ak);
            float4 ba = *(const float4*)(beta  + ak);
            va.x = (xa.x-mu)*rs*ga.x + ba.x;
            va.y = (xa.y-mu)*rs*ga.y + ba.y;
            va.z = (xa.z-mu)*rs*ga.z + ba.z;
            va.w = (xa.w-mu)*rs*ga.w + ba.w;
        } else va = make_float4(0.f,0.f,0.f,0.f);
        wb0 = *(const float4*)(w + (size_t)bk*HID + bn);
        wb1 = *(const float4*)(w + (size_t)bk*HID + bn + 4);
    }
    As[0][ak+0][arow] = va.x;
    As[0][ak+1][arow] = va.y;
    As[0][ak+2][arow] = va.z;
    As[0][ak+3][arow] = va.w;
    *(float4*)&Bs[0][bk][bn]   = wb0;
    *(float4*)&Bs[0][bk][bn+4] = wb1;
    __syncthreads();

    int buf = 0;
    const int T = DIM/16;   // 32
    for (int t=0; t<T; t++){
        if (t+1 < T){
            int k0 = (t+1)*16;
            if (av){
                float4 xa = *(const float4*)(xrow + k0 + ak);
                float4 ga = *(const float4*)(gamma + k0 + ak);
                float4 ba = *(const float4*)(beta  + k0 + ak);
                va.x = (xa.x-mu)*rs*ga.x + ba.x;
                va.y = (xa.y-mu)*rs*ga.y + ba.y;
                va.z = (xa.z-mu)*rs*ga.z + ba.z;
                va.w = (xa.w-mu)*rs*ga.w + ba.w;
            } else va = make_float4(0.f,0.f,0.f,0.f);
            wb0 = *(const float4*)(w + (size_t)(k0+bk)*HID + bn);
            wb1 = *(const float4*)(w + (size_t)(k0+bk)*HID + bn + 4);
        }
        #pragma unroll
        for (int kk=0;kk<16;kk++){
            const u64* ap = (const u64*)&As[buf][kk][wid*8];
            u64 a0 = ap[0], a1 = ap[1], a2 = ap[2], a3 = ap[3];
            #pragma unroll
            for (int jj=0;jj<8;jj++){
                float bv = Bs[buf][kk][lane + 32*jj];
                u64 b2 = pk2(bv, bv);
                ffma2(acc[0][jj], a0, b2);
                ffma2(acc[1][jj], a1, b2);
                ffma2(acc[2][jj], a2, b2);
                ffma2(acc[3][jj], a3, b2);
            }
        }
        if (t+1 < T){
            int nb = buf ^ 1;
            As[nb][ak+0][arow] = va.x;
            As[nb][ak+1][arow] = va.y;
            As[nb][ak+2][arow] = va.z;
            As[nb][ak+3][arow] = va.w;
            *(float4*)&Bs[nb][bk][bn]   = wb0;
            *(float4*)&Bs[nb][bk][bn+4] = wb1;
            __syncthreads();
            buf = nb;
        }
    }
    // epilogue: gelu + store
    int r0 = m0 + wid*8;
    #pragma unroll
    for (int rp=0;rp<4;rp++){
        int rlo = r0 + 2*rp, rhi = rlo + 1;
        bool slo = rlo < M1, shi = rhi < M1;
        #pragma unroll
        for (int jj=0;jj<8;jj++){
            float lo, hi;
            upk2(acc[rp][jj], lo, hi);
            int col = lane + 32*jj;
            if (slo) g_h[(size_t)rlo*HID + col] = gelu_exact(lo);
            if (shi) g_h[(size_t)rhi*HID + col] = gelu_exact(hi);
        }
    }
}

// ---------------- K2: gcontrib[f,j] = sum_k h[f,0,k] * w1[256+k, j] ----------------
__global__ void gc_kernel(const float* __restrict__ w1){
    __shared__ float h0[HID];
    int f = blockIdx.x, j = threadIdx.x;
    h0[j] = g_h[(size_t)(f*NTOK)*HID + j];
    __syncthreads();
    float acc = 0.f;
    #pragma unroll 8
    for (int k=0;k<HID;k++)
        acc += h0[k] * w1[(size_t)(HID+k)*HID + j];
    g_gc[f*HID + j] = acc;
}

// ---------------- K3: score = tanh(gelu(h@w1_top + gc) @ w2) ----------------
// BM=128, BN=256 (reduced in epilogue), BK=16, 512 threads, grid 147 (1 wave).
__global__ __launch_bounds__(512,1) void score_kernel(const float* __restrict__ w1,
                             const float* __restrict__ w2){
    __shared__ float As[2][16][128];
    __shared__ float Bs[2][16][256];
    int tid = threadIdx.x;
    int lane = tid & 31, wid = tid >> 5;
    int m0 = blockIdx.x * 128;

    // A loader
    int arow = tid & 127;
    int ak   = (tid >> 7) * 4;
    int m = m0 + arow;
    int f_ld = m / NSP;
    int i_ld = m - f_ld*NSP;
    const float* hrow = g_h + (size_t)(f_ld*NTOK + 1 + i_ld)*HID;
    // B loader
    int bk = tid >> 5;
    int bn = (tid & 31) * 8;

    u64 acc[4][8];
    #pragma unroll
    for (int i=0;i<4;i++)
        #pragma unroll
        for (int j=0;j<8;j++) acc[i][j] = 0ull;

    float4 va; float4 wb0, wb1;
    {
        va  = *(const float4*)(hrow + ak);
        wb0 = *(const float4*)(w1 + (size_t)bk*HID + bn);
        wb1 = *(const float4*)(w1 + (size_t)bk*HID + bn + 4);
    }
    As[0][ak+0][arow] = va.x;
    As[0][ak+1][arow] = va.y;
    As[0][ak+2][arow] = va.z;
    As[0][ak+3][arow] = va.w;
    *(float4*)&Bs[0][bk][bn]   = wb0;
    *(float4*)&Bs[0][bk][bn+4] = wb1;
    __syncthreads();

    int buf = 0;
    const int T = HID/16;  // 16
    for (int t=0;t<T;t++){
        if (t+1 < T){
            int k0 = (t+1)*16;
            va  = *(const float4*)(hrow + k0 + ak);
            wb0 = *(const float4*)(w1 + (size_t)(k0+bk)*HID + bn);
            wb1 = *(const float4*)(w1 + (size_t)(k0+bk)*HID + bn + 4);
        }
        #pragma unroll
        for (int kk=0;kk<16;kk++){
            const u64* ap = (const u64*)&As[buf][kk][wid*8];
            u64 a0 = ap[0], a1 = ap[1], a2 = ap[2], a3 = ap[3];
            #pragma unroll
            for (int jj=0;jj<8;jj++){
                float bv = Bs[buf][kk][lane + 32*jj];
                u64 b2 = pk2(bv, bv);
                ffma2(acc[0][jj], a0, b2);
                ffma2(acc[1][jj], a1, b2);
                ffma2(acc[2][jj], a2, b2);
                ffma2(acc[3][jj], a3, b2);
            }
        }
        if (t+1 < T){
            int nb = buf ^ 1;
            As[nb][ak+0][arow] = va.x;
            As[nb][ak+1][arow] = va.y;
            As[nb][ak+2][arow] = va.z;
            As[nb][ak+3][arow] = va.w;
            *(float4*)&Bs[nb][bk][bn]   = wb0;
            *(float4*)&Bs[nb][bk][bn+4] = wb1;
            __syncthreads();
            buf = nb;
        }
    }
    // epilogue: u + gc -> gelu -> *w2 -> row reduce
    int rbase = m0 + wid*8;
    int fr[8];
    #pragma unroll
    for (int rr=0;rr<8;rr++) fr[rr] = (rbase + rr) / NSP;
    float s[8];
    #pragma unroll
    for (int rr=0;rr<8;rr++) s[rr] = 0.f;
    #pragma unroll
    for (int jj=0;jj<8;jj++){
        int j = lane + 32*jj;
        float w2v = w2[j];
        #pragma unroll
        for (int rp=0;rp<4;rp++){
            float lo, hi;
            upk2(acc[rp][jj], lo, hi);
            float glo = g_gc[fr[2*rp]*HID + j];
            float ghi = g_gc[fr[2*rp+1]*HID + j];
            s[2*rp]   += gelu_exact(lo + glo) * w2v;
            s[2*rp+1] += gelu_exact(hi + ghi) * w2v;
        }
    }
    #pragma unroll
    for (int rr=0;rr<8;rr++){
        float v = s[rr];
        #pragma unroll
        for (int o=16;o>0;o>>=1) v += __shfl_xor_sync(0xFFFFFFFFu, v, o);
        s[rr] = v;
    }
    if (lane == 0){
        #pragma unroll
        for (int rr=0;rr<8;rr++)
            g_score[rbase + rr] = tanhf(s[rr]);
    }
}

// ---------------- K4: top-49 selection, exact, 2-bit/step binary search ----------------
// grid = BF*2 (192), 512 threads = 16 warps; warp handles 8 samples.
// Exact dyadic 1/256 atomics into global g_ind (order-independent, deterministic).
__global__ __launch_bounds__(512) void select_kernel(const float* __restrict__ noise){
    __shared__ float sps[NSP];
    int bf   = blockIdx.x >> 1;
    int half = blockIdx.x & 1;
    int wid = threadIdx.x >> 5, lane = threadIdx.x & 31;
    if (threadIdx.x < NSP) sps[threadIdx.x] = g_score[bf*NSP + threadIdx.x];
    __syncthreads();

    for (int s8=0; s8<8; s8++){
        int s = half*128 + wid*8 + s8;
        const float* np = noise + (size_t)(bf*NS + s)*NSP;
        u64 K[7];
        #pragma unroll
        for (int c=0;c<7;c++){
            int l = c*32 + lane;
            u64 kk = 0ull;
            if (l < NSP){
                float p = sps[l] + SIGMA * np[l];
                unsigned u = __float_as_uint(p);
                u ^= (u & 0x80000000u) ? 0xFFFFFFFFu : 0x80000000u;   // monotone key
                kk = ((u64)u << 8) | (unsigned)(255 - l);             // tie: lower l wins
            }
            K[c] = kk;
        }
        // 2 bits per step: count keys >= pref|{01,10,11}, packed in 10-bit fields
        u64 pref = 0ull;
        #pragma unroll 1
        for (int b=38;b>=0;b-=2){
            u64 c01 = pref | (1ull << b);
            u64 c10 = pref | (2ull << b);
            u64 c11 = pref | (3ull << b);
            unsigned cnt = 0;
            #pragma unroll
            for (int c=0;c<7;c++){
                cnt += (K[c] >= c01) ? 1u : 0u;
                cnt += (K[c] >= c10) ? (1u<<10) : 0u;
                cnt += (K[c] >= c11) ? (1u<<20) : 0u;
            }
            cnt = __reduce_add_sync(0xFFFFFFFFu, cnt);
            if ((cnt >> 20) >= TOPK)            pref = c11;
            else if (((cnt >> 10) & 1023u) >= TOPK) pref = c10;
            else if ((cnt & 1023u) >= TOPK)     pref = c01;
        }
        // selected = key >= pref (exactly 49); position = prefix count in l order
        int pre = 0;
        #pragma unroll
        for (int c=0;c<7;c++){
            bool sel = (K[c] >= pref);
            unsigned bal = __ballot_sync(0xFFFFFFFFu, sel);
            int l = c*32 + lane;
            if (sel){
                int k = pre + __popc(bal & ((1u<<lane)-1u));
                atomicAdd(&g_ind[((size_t)bf*TOPK + k)*NSP + l], 1.0f/NS);
            }
            pre += __popc(bal);
        }
    }
}

// ---------------- K5: out = [cls ; ind @ spat] ----------------
// grid (BF, 4), 128 threads; ind transposed into smem padded to 50.
__global__ void output_kernel(const float* __restrict__ x, float* __restrict__ out){
    __shared__ __align__(8) float indsT[NSP][TOPK+1];   // 39.2 KB
    int bf = blockIdx.x;
    int d  = blockIdx.y * 128 + threadIdx.x;
    int t  = threadIdx.x;
    #pragma unroll 1
    for (int k=0;k<TOPK;k++)
        for (int l=t; l<NSP; l+=128)
            indsT[l][k] = g_ind[((size_t)bf*TOPK + k)*NSP + l];
    for (int l=t; l<NSP; l+=128) indsT[l][TOPK] = 0.f;
    __syncthreads();

    u64 acc[25];
    #pragma unroll
    for (int kp=0;kp<25;kp++) acc[kp] = 0ull;
    const float* xb = x + (size_t)(bf*NTOK)*DIM + d;
    #pragma unroll 1
    for (int l=0;l<NSP;l++){
        float xv = xb[(size_t)(l+1)*DIM];
        u64 x2 = pk2(xv, xv);
        const u64* row = (const u64*)indsT[l];
        #pragma unroll
        for (int kp=0;kp<25;kp++) ffma2(acc[kp], x2, row[kp]);
    }
    float* ob = out + (size_t)(bf*(1+TOPK))*DIM + d;
    ob[0] = xb[0];   // cls passthrough
    #pragma unroll
    for (int kp=0;kp<25;kp++){
        float lo, hi;
        upk2(acc[kp], lo, hi);
        ob[(size_t)(2*kp+1)*DIM] = lo;
        if (kp < 24) ob[(size_t)(2*kp+2)*DIM] = hi;
    }
}

// ---------------- launcher ----------------
extern "C" void kernel_launch(void* const* d_in, const int* in_sizes, int n_in,
                              void* d_out, int out_size){
    const float* x     = (const float*)d_in[0];
    const float* noise = (const float*)d_in[1];
    const float* gamma = (const float*)d_in[2];
    const float* beta  = (const float*)d_in[3];
    const float* w_in  = (const float*)d_in[4];
    const float* w1    = (const float*)d_in[5];
    const float* w2    = (const float*)d_in[6];
    float* out = (float*)d_out;

    stats_kernel<<<(M1+7)/8, 256>>>(x);
    gemm1_kernel<<<(M1+127)/128, 512>>>(x, gamma, beta, w_in);
    gc_kernel<<<BF, 256>>>(w1);
    score_kernel<<<M3/128, 512>>>(w1, w2);
    select_kernel<<<BF*2, 512>>>(noise);
    dim3 g5(BF, 4);
    output_kernel<<<g5, 128>>>(x, out);
}